// round 16
// baseline (speedup 1.0000x reference)
#include <cuda_runtime.h>

// LIF neuron forward: T=8 leaky-integrate-fire scan.
// 128 MiB read + 128 MiB write per launch.
//
// R15 experiment: single-wave persistent grid-stride launch. All memory-side
// levers are falsified (MLP, store batching, L2 pinning x2, 256-bit: all
// neutral/regression; frozen config verified 5x at 45.1-46.1 us wall).
// Launch geometry is the one untested variable: prior variants ran 4096
// one-shot CTAs = ~7 waves at occ 4 CTAs/SM => partial tail wave (BW
// unsaturated for the tail) + ~6 wave transitions. This version: grid =
// 148 SMs x 4 = 592 CTAs, one wave, grid-stride loop; no tail, no
// transitions. Memory config byte-identical to the frozen kernel
// (createpolicy frac=0.65 cache_hint loads, st.global.cs stores,
// read burst -> register recurrence -> write burst per tile).

constexpr int T_STEPS = 8;
constexpr int NUM_SMS = 148;      // B200 sm_100a
constexpr int CTAS_PER_SM = 4;    // matches __launch_bounds__(256, 4)

__device__ __forceinline__ float4 ldg_hint(const float4* p, unsigned long long pol) {
    float4 v;
    asm volatile("ld.global.nc.L2::cache_hint.v4.f32 {%0,%1,%2,%3}, [%4], %5;"
                 : "=f"(v.x), "=f"(v.y), "=f"(v.z), "=f"(v.w)
                 : "l"(p), "l"(pol));
    return v;
}

__device__ __forceinline__ void stg_evict_first(float4* p, float4 v) {
    asm volatile("st.global.cs.v4.f32 [%0], {%1,%2,%3,%4};"
                 :: "l"(p), "f"(v.x), "f"(v.y), "f"(v.z), "f"(v.w)
                 : "memory");
}

__global__ __launch_bounds__(256, 4) void lif_kernel(
    const float4* __restrict__ x,
    float4* __restrict__ out,
    int n4)               // float4 elements per timestep
{
    unsigned long long pol;
    asm volatile("createpolicy.fractional.L2::evict_last.b64 %0, 0.65;" : "=l"(pol));

    const int stride = gridDim.x * blockDim.x;

    for (int i = blockIdx.x * blockDim.x + threadIdx.x; i < n4; i += stride) {
        // Phase 1: all 8 strided loads back-to-back (one read burst).
        float4 xv[T_STEPS];
#pragma unroll
        for (int t = 0; t < T_STEPS; t++) {
            xv[t] = ldg_hint(&x[(size_t)t * n4 + i], pol);
        }

        // Phase 2: recurrence entirely in registers; spike overwrites xv[t].
        float4 mem = make_float4(0.f, 0.f, 0.f, 0.f);
#pragma unroll
        for (int t = 0; t < T_STEPS; t++) {
            float sx, sy, sz, sw;

            mem.x = 0.5f * (mem.x + xv[t].x);
            sx = (mem.x > 0.5f) ? 1.0f : 0.0f;
            mem.x = (mem.x > 0.5f) ? 0.0f : mem.x;

            mem.y = 0.5f * (mem.y + xv[t].y);
            sy = (mem.y > 0.5f) ? 1.0f : 0.0f;
            mem.y = (mem.y > 0.5f) ? 0.0f : mem.y;

            mem.z = 0.5f * (mem.z + xv[t].z);
            sz = (mem.z > 0.5f) ? 1.0f : 0.0f;
            mem.z = (mem.z > 0.5f) ? 0.0f : mem.z;

            mem.w = 0.5f * (mem.w + xv[t].w);
            sw = (mem.w > 0.5f) ? 1.0f : 0.0f;
            mem.w = (mem.w > 0.5f) ? 0.0f : mem.w;

            xv[t] = make_float4(sx, sy, sz, sw);
        }

        // Phase 3: all 8 stores back-to-back (one write burst).
#pragma unroll
        for (int t = 0; t < T_STEPS; t++) {
            stg_evict_first(&out[(size_t)t * n4 + i], xv[t]);
        }
    }
}

extern "C" void kernel_launch(void* const* d_in, const int* in_sizes, int n_in,
                              void* d_out, int out_size)
{
    const float* x = (const float*)d_in[0];
    float* out = (float*)d_out;

    int total = in_sizes[0];            // 33,554,432
    int per_t = total / T_STEPS;        // 4,194,304
    int n4 = per_t / 4;                 // 1,048,576 float4 per timestep

    int threads = 256;
    int blocks = NUM_SMS * CTAS_PER_SM; // 592 = exactly one wave

    lif_kernel<<<blocks, threads>>>(
        (const float4*)x, (float4*)out, n4);
}

// round 17
// speedup vs baseline: 1.1375x; 1.1375x over previous
#include <cuda_runtime.h>

// LIF neuron forward: T=8 leaky-integrate-fire scan.
// 128 MiB read + 128 MiB write per launch.
//
// FINAL (frozen; reverted after R15 persistent-grid regression). This
// workload is memory-roofline-bound at ~5.7 TB/s sustained mixed 50/50 R/W
// on this part (~72% of 8 TB/s spec; remainder is bus-turnaround on
// interleaved read/write streams). Verified across 5 hardware runs: wall
// 45.09/45.09/46.08/45.18/45.22 us (noise +-1 us), kernel 37.3-37.6 us,
// rel_err 0.0 on all.
//
// Complete falsification sweep (each a structurally distinct kernel):
//   - MLP 3 vs 8 (reg-hoisted load batch)      -> neutral
//   - occupancy 42% vs 62%                     -> neutral
//   - store batching (phase-separated bursts)  -> neutral
//   - L2 evict_last pinning, frac 1.0 and 0.65 -> neutral (no cross-replay
//     residency survives in this harness)
//   - 256-bit v8.b32 transactions              -> regression (-2 us wall)
//   - persistent single-wave grid (592 CTAs)   -> regression (-6 us wall;
//     grid-stride serializes cross-tile MLP; oversubscribed one-shot grids
//     let the HW scheduler overlap waves for free)
//
// Config: createpolicy frac=0.65 cache_hint loads + st.global.cs stores,
// read burst -> register recurrence -> write burst, 4096 one-shot CTAs.

constexpr int T_STEPS = 8;

__device__ __forceinline__ float4 ldg_hint(const float4* p, unsigned long long pol) {
    float4 v;
    asm volatile("ld.global.nc.L2::cache_hint.v4.f32 {%0,%1,%2,%3}, [%4], %5;"
                 : "=f"(v.x), "=f"(v.y), "=f"(v.z), "=f"(v.w)
                 : "l"(p), "l"(pol));
    return v;
}

__device__ __forceinline__ void stg_evict_first(float4* p, float4 v) {
    asm volatile("st.global.cs.v4.f32 [%0], {%1,%2,%3,%4};"
                 :: "l"(p), "f"(v.x), "f"(v.y), "f"(v.z), "f"(v.w)
                 : "memory");
}

__global__ __launch_bounds__(256, 4) void lif_kernel(
    const float4* __restrict__ x,
    float4* __restrict__ out,
    int n4)               // float4 elements per timestep
{
    int i = blockIdx.x * blockDim.x + threadIdx.x;
    if (i >= n4) return;

    unsigned long long pol;
    asm volatile("createpolicy.fractional.L2::evict_last.b64 %0, 0.65;" : "=l"(pol));

    // Phase 1: all 8 strided loads back-to-back (one read burst).
    float4 xv[T_STEPS];
#pragma unroll
    for (int t = 0; t < T_STEPS; t++) {
        xv[t] = ldg_hint(&x[(size_t)t * n4 + i], pol);
    }

    // Phase 2: recurrence entirely in registers; spike overwrites xv[t].
    float4 mem = make_float4(0.f, 0.f, 0.f, 0.f);
#pragma unroll
    for (int t = 0; t < T_STEPS; t++) {
        float sx, sy, sz, sw;

        mem.x = 0.5f * (mem.x + xv[t].x);
        sx = (mem.x > 0.5f) ? 1.0f : 0.0f;
        mem.x = (mem.x > 0.5f) ? 0.0f : mem.x;

        mem.y = 0.5f * (mem.y + xv[t].y);
        sy = (mem.y > 0.5f) ? 1.0f : 0.0f;
        mem.y = (mem.y > 0.5f) ? 0.0f : mem.y;

        mem.z = 0.5f * (mem.z + xv[t].z);
        sz = (mem.z > 0.5f) ? 1.0f : 0.0f;
        mem.z = (mem.z > 0.5f) ? 0.0f : mem.z;

        mem.w = 0.5f * (mem.w + xv[t].w);
        sw = (mem.w > 0.5f) ? 1.0f : 0.0f;
        mem.w = (mem.w > 0.5f) ? 0.0f : mem.w;

        xv[t] = make_float4(sx, sy, sz, sw);
    }

    // Phase 3: all 8 stores back-to-back (one write burst).
#pragma unroll
    for (int t = 0; t < T_STEPS; t++) {
        stg_evict_first(&out[(size_t)t * n4 + i], xv[t]);
    }
}

extern "C" void kernel_launch(void* const* d_in, const int* in_sizes, int n_in,
                              void* d_out, int out_size)
{
    const float* x = (const float*)d_in[0];
    float* out = (float*)d_out;

    int total = in_sizes[0];            // 33,554,432
    int per_t = total / T_STEPS;        // 4,194,304
    int n4 = per_t / 4;                 // 1,048,576 float4 per timestep

    int threads = 256;
    int blocks = (n4 + threads - 1) / threads;   // 4096

    lif_kernel<<<blocks, threads>>>(
        (const float4*)x, (float4*)out, n4);
}